// round 3
// baseline (speedup 1.0000x reference)
#include <cuda_runtime.h>
#include <cuda_bf16.h>
#include <cstdint>

// GRU fused kernel: B=16, T=60, S=2000, C=64, H=64.
// N = B*S = 32000 independent sequences; each CTA owns 64 of them and runs
// all 60 timesteps locally with weights + hidden state in SMEM.
// GEMMs use mma.sync m16n8k16 bf16 with a 3-term hi/lo split for ~fp32 accuracy.

namespace {

constexpr int kT = 60, kS = 2000, kC = 64, kH = 64, kG = 192;
constexpr int TILE_M = 64;
constexpr int PITCH = 72;            // bf16 elems per smem row (144 B) -> conflict-free ldmatrix
constexpr int THREADS = 256;
constexpr int NROWS = 16 * 2000;     // 32000

// dynamic smem byte offsets
constexpr int OFF_XS_HI = 0;
constexpr int OFF_XS_LO = OFF_XS_HI + TILE_M * PITCH * 2;
constexpr int OFF_HS_HI = OFF_XS_LO + TILE_M * PITCH * 2;
constexpr int OFF_HS_LO = OFF_HS_HI + TILE_M * PITCH * 2;
constexpr int OFF_WIH_HI = OFF_HS_LO + TILE_M * PITCH * 2;
constexpr int OFF_WIH_LO = OFF_WIH_HI + kG * PITCH * 2;
constexpr int OFF_WHH_HI = OFF_WIH_LO + kG * PITCH * 2;
constexpr int OFF_WHH_LO = OFF_WHH_HI + kG * PITCH * 2;
constexpr int OFF_BRZ = OFF_WHH_LO + kG * PITCH * 2;
constexpr int OFF_BIN = OFF_BRZ + 128 * 4;
constexpr int OFF_BHN = OFF_BIN + 64 * 4;
constexpr int SMEM_BYTES = OFF_BHN + 64 * 4;   // = 149504-ish, fits 227KB

__device__ __forceinline__ uint32_t smem_u32(const void* p) {
  return (uint32_t)__cvta_generic_to_shared(p);
}

__device__ __forceinline__ void ldsm4(uint32_t r[4], uint32_t addr) {
  asm volatile("ldmatrix.sync.aligned.m8n8.x4.shared.b16 {%0,%1,%2,%3}, [%4];\n"
               : "=r"(r[0]), "=r"(r[1]), "=r"(r[2]), "=r"(r[3]) : "r"(addr));
}
__device__ __forceinline__ void ldsm2(uint32_t r[2], uint32_t addr) {
  asm volatile("ldmatrix.sync.aligned.m8n8.x2.shared.b16 {%0,%1}, [%2];\n"
               : "=r"(r[0]), "=r"(r[1]) : "r"(addr));
}
__device__ __forceinline__ void mma16816(float d[4], const uint32_t a[4], const uint32_t b[2]) {
  asm volatile(
      "mma.sync.aligned.m16n8k16.row.col.f32.bf16.bf16.f32 "
      "{%0,%1,%2,%3},{%4,%5,%6,%7},{%8,%9},{%0,%1,%2,%3};\n"
      : "+f"(d[0]), "+f"(d[1]), "+f"(d[2]), "+f"(d[3])
      : "r"(a[0]), "r"(a[1]), "r"(a[2]), "r"(a[3]), "r"(b[0]), "r"(b[1]));
}

// 3-term split product: acc += (ah+al)*(bh+bl) dropping al*bl (~2^-16 rel)
__device__ __forceinline__ void mma3(float d[4], const uint32_t ah[4], const uint32_t al[4],
                                     uint32_t whi_addr, uint32_t wlo_addr) {
  uint32_t bh[2], bl[2];
  ldsm2(bh, whi_addr);
  ldsm2(bl, wlo_addr);
  mma16816(d, ah, bh);
  mma16816(d, ah, bl);
  mma16816(d, al, bh);
}

// store two floats split into hi/lo bf16 arrays (4B-aligned pair stores)
__device__ __forceinline__ void split_store2(float a, float b,
                                             __nv_bfloat16* hip, __nv_bfloat16* lop) {
  __nv_bfloat16 ah = __float2bfloat16(a);
  __nv_bfloat16 bh = __float2bfloat16(b);
  __nv_bfloat16 al = __float2bfloat16(a - __bfloat162float(ah));
  __nv_bfloat16 bl = __float2bfloat16(b - __bfloat162float(bh));
  __nv_bfloat162 h2; h2.x = ah; h2.y = bh;
  __nv_bfloat162 l2; l2.x = al; l2.y = bl;
  *reinterpret_cast<__nv_bfloat162*>(hip) = h2;
  *reinterpret_cast<__nv_bfloat162*>(lop) = l2;
}

__device__ __forceinline__ float fsigmoid(float x) {
  return __fdividef(1.0f, 1.0f + __expf(-x));
}
__device__ __forceinline__ float ftanh_acc(float x) {
  return __fdividef(2.0f, 1.0f + __expf(-2.0f * x)) - 1.0f;
}

}  // namespace

__global__ void __launch_bounds__(THREADS, 1)
gru_fused_kernel(const float* __restrict__ chars,
                 const float* __restrict__ Wih,
                 const float* __restrict__ Whh,
                 const float* __restrict__ bih,
                 const float* __restrict__ bhh,
                 float* __restrict__ out) {
  extern __shared__ char smem[];
  __nv_bfloat16* xs_hi = reinterpret_cast<__nv_bfloat16*>(smem + OFF_XS_HI);
  __nv_bfloat16* xs_lo = reinterpret_cast<__nv_bfloat16*>(smem + OFF_XS_LO);
  __nv_bfloat16* hs_hi = reinterpret_cast<__nv_bfloat16*>(smem + OFF_HS_HI);
  __nv_bfloat16* hs_lo = reinterpret_cast<__nv_bfloat16*>(smem + OFF_HS_LO);
  __nv_bfloat16* wih_hi = reinterpret_cast<__nv_bfloat16*>(smem + OFF_WIH_HI);
  __nv_bfloat16* wih_lo = reinterpret_cast<__nv_bfloat16*>(smem + OFF_WIH_LO);
  __nv_bfloat16* whh_hi = reinterpret_cast<__nv_bfloat16*>(smem + OFF_WHH_HI);
  __nv_bfloat16* whh_lo = reinterpret_cast<__nv_bfloat16*>(smem + OFF_WHH_LO);
  float* brz = reinterpret_cast<float*>(smem + OFF_BRZ);
  float* bin_s = reinterpret_cast<float*>(smem + OFF_BIN);
  float* bhn_s = reinterpret_cast<float*>(smem + OFF_BHN);

  const int tid = threadIdx.x;
  const int lane = tid & 31;
  const int wid = tid >> 5;
  const int wm = wid & 3;   // m-tile (16 rows each)
  const int wn = wid >> 2;  // n-half (32 gate-cols per region)
  const int blk_n0 = blockIdx.x * TILE_M;

  // h = 0 : hs_hi and hs_lo are contiguous; TILE_M*PITCH u32 words = both arrays
  {
    uint32_t* p = reinterpret_cast<uint32_t*>(smem + OFF_HS_HI);
    for (int i = tid; i < TILE_M * PITCH; i += THREADS) p[i] = 0u;
  }

  // split weights into hi/lo bf16 (padded pitch)
  for (int i = tid; i < kG * kC; i += THREADS) {
    const int g = i >> 6, c = i & 63;
    const float w1 = Wih[i];
    const __nv_bfloat16 h1 = __float2bfloat16(w1);
    wih_hi[g * PITCH + c] = h1;
    wih_lo[g * PITCH + c] = __float2bfloat16(w1 - __bfloat162float(h1));
    const float w2 = Whh[i];
    const __nv_bfloat16 h2 = __float2bfloat16(w2);
    whh_hi[g * PITCH + c] = h2;
    whh_lo[g * PITCH + c] = __float2bfloat16(w2 - __bfloat162float(h2));
  }
  if (tid < 128) brz[tid] = bih[tid] + bhh[tid];
  if (tid < 64) {
    bin_s[tid] = bih[128 + tid];
    bhn_s[tid] = bhh[128 + tid];
  }
  __syncthreads();

  // hoist biases into registers (accumulator init values)
  float biasR[4][2], biasZ[4][2], biasN[4][2], biasHN[4][2];
  const int col0 = wn * 32 + (lane & 3) * 2;
#pragma unroll
  for (int jt = 0; jt < 4; ++jt) {
    const int c0 = col0 + jt * 8;
    biasR[jt][0] = brz[c0];
    biasR[jt][1] = brz[c0 + 1];
    biasZ[jt][0] = brz[64 + c0];
    biasZ[jt][1] = brz[64 + c0 + 1];
    biasN[jt][0] = bin_s[c0];
    biasN[jt][1] = bin_s[c0 + 1];
    biasHN[jt][0] = bhn_s[c0];
    biasHN[jt][1] = bhn_s[c0 + 1];
  }

  // per-thread x source pointer: row = tid/4 in tile, 16 floats at (tid%4)*16
  const int xr = tid >> 2;
  const int xc = (tid & 3) << 4;
  const int nrow = blk_n0 + xr;
  const int bb = nrow / kS;
  const int ss = nrow - bb * kS;
  const float* px = chars + ((size_t)bb * kT * kS + (size_t)ss) * kC + xc;

  // ldmatrix addresses
  const int a_row = wm * 16 + (lane & 15);
  const int a_byte = a_row * (PITCH * 2) + ((lane >> 4) << 4);
  const uint32_t axh_base = smem_u32(xs_hi) + a_byte;
  const uint32_t axl_base = smem_u32(xs_lo) + a_byte;
  const uint32_t ahh_base = smem_u32(hs_hi) + a_byte;
  const uint32_t ahl_base = smem_u32(hs_lo) + a_byte;

  const int bi = lane & 15;
  const int b_byte = (bi & 7) * (PITCH * 2) + ((bi >> 3) << 4);
  const uint32_t wihh_b = smem_u32(wih_hi) + b_byte;
  const uint32_t wihl_b = smem_u32(wih_lo) + b_byte;
  const uint32_t whhh_b = smem_u32(whh_hi) + b_byte;
  const uint32_t whhl_b = smem_u32(whh_lo) + b_byte;

  const int row0 = wm * 16 + (lane >> 2);
  constexpr int ZOFF = 64 * PITCH * 2;    // byte offset to z-gate rows of W
  constexpr int NOFF = 128 * PITCH * 2;   // byte offset to n-gate rows of W

  for (int t = 0; t < kT; ++t) {
    // ---- stage x_t into smem as hi/lo bf16 ----
    const float4 v0 = *reinterpret_cast<const float4*>(px);
    const float4 v1 = *reinterpret_cast<const float4*>(px + 4);
    const float4 v2 = *reinterpret_cast<const float4*>(px + 8);
    const float4 v3 = *reinterpret_cast<const float4*>(px + 12);
    px += kS * kC;
    {
      __nv_bfloat16* hp = xs_hi + xr * PITCH + xc;
      __nv_bfloat16* lp = xs_lo + xr * PITCH + xc;
      split_store2(v0.x, v0.y, hp + 0, lp + 0);
      split_store2(v0.z, v0.w, hp + 2, lp + 2);
      split_store2(v1.x, v1.y, hp + 4, lp + 4);
      split_store2(v1.z, v1.w, hp + 6, lp + 6);
      split_store2(v2.x, v2.y, hp + 8, lp + 8);
      split_store2(v2.z, v2.w, hp + 10, lp + 10);
      split_store2(v3.x, v3.y, hp + 12, lp + 12);
      split_store2(v3.z, v3.w, hp + 14, lp + 14);
    }
    __syncthreads();

    // ---- GEMMs: acc = bias + x@Wih^T (+ h@Whh^T for r,z; separate for n) ----
    float accR[4][4], accZ[4][4], accN[4][4], accHN[4][4];
#pragma unroll
    for (int jt = 0; jt < 4; ++jt)
#pragma unroll
      for (int e = 0; e < 4; ++e) {
        accR[jt][e] = biasR[jt][e & 1];
        accZ[jt][e] = biasZ[jt][e & 1];
        accN[jt][e] = biasN[jt][e & 1];
        accHN[jt][e] = biasHN[jt][e & 1];
      }

#pragma unroll
    for (int k = 0; k < 4; ++k) {
      const int k32 = k * 32;
      uint32_t axh[4], axl[4], ahh[4], ahl[4];
      ldsm4(axh, axh_base + k32);
      ldsm4(axl, axl_base + k32);
      ldsm4(ahh, ahh_base + k32);
      ldsm4(ahl, ahl_base + k32);
#pragma unroll
      for (int jt = 0; jt < 4; ++jt) {
        const int gb = (wn * 32 + jt * 8) * (PITCH * 2);
        mma3(accR[jt], axh, axl, wihh_b + gb + k32, wihl_b + gb + k32);
        mma3(accZ[jt], axh, axl, wihh_b + gb + ZOFF + k32, wihl_b + gb + ZOFF + k32);
        mma3(accN[jt], axh, axl, wihh_b + gb + NOFF + k32, wihl_b + gb + NOFF + k32);
        mma3(accR[jt], ahh, ahl, whhh_b + gb + k32, whhl_b + gb + k32);
        mma3(accZ[jt], ahh, ahl, whhh_b + gb + ZOFF + k32, whhl_b + gb + ZOFF + k32);
        mma3(accHN[jt], ahh, ahl, whhh_b + gb + NOFF + k32, whhl_b + gb + NOFF + k32);
      }
    }
    __syncthreads();

    // ---- elementwise GRU update; write new h (hi/lo split) ----
#pragma unroll
    for (int jt = 0; jt < 4; ++jt) {
      const int c = col0 + jt * 8;
#pragma unroll
      for (int half = 0; half < 2; ++half) {
        const int row = row0 + half * 8;
        const int e0 = half * 2, e1 = half * 2 + 1;
        const float r0 = fsigmoid(accR[jt][e0]);
        const float r1 = fsigmoid(accR[jt][e1]);
        const float z0 = fsigmoid(accZ[jt][e0]);
        const float z1 = fsigmoid(accZ[jt][e1]);
        const float nn0 = ftanh_acc(accN[jt][e0] + r0 * accHN[jt][e0]);
        const float nn1 = ftanh_acc(accN[jt][e1] + r1 * accHN[jt][e1]);
        const __nv_bfloat162 hph =
            *reinterpret_cast<__nv_bfloat162*>(hs_hi + row * PITCH + c);
        const __nv_bfloat162 hpl =
            *reinterpret_cast<__nv_bfloat162*>(hs_lo + row * PITCH + c);
        const float hp0 = __bfloat162float(hph.x) + __bfloat162float(hpl.x);
        const float hp1 = __bfloat162float(hph.y) + __bfloat162float(hpl.y);
        const float hn0 = nn0 + z0 * (hp0 - nn0);
        const float hn1 = nn1 + z1 * (hp1 - nn1);
        split_store2(hn0, hn1, hs_hi + row * PITCH + c, hs_lo + row * PITCH + c);
      }
    }
    // next iteration's __syncthreads (after x staging) publishes h before GEMM reads
  }

  __syncthreads();
  // ---- write final h: out[n][h], n = b*S + s ordering matches tile rows ----
  {
    float* po = out + (size_t)nrow * kH + xc;
#pragma unroll
    for (int q = 0; q < 16; ++q) {
      const int c = xc + q;
      po[q] = __bfloat162float(hs_hi[xr * PITCH + c]) +
              __bfloat162float(hs_lo[xr * PITCH + c]);
    }
  }
}

extern "C" void kernel_launch(void* const* d_in, const int* in_sizes, int n_in,
                              void* d_out, int out_size) {
  const float* chars = (const float*)d_in[0];
  const float* Wih = (const float*)d_in[1];
  const float* Whh = (const float*)d_in[2];
  const float* bih = (const float*)d_in[3];
  const float* bhh = (const float*)d_in[4];
  float* out = (float*)d_out;

  cudaFuncSetAttribute(gru_fused_kernel,
                       cudaFuncAttributeMaxDynamicSharedMemorySize, SMEM_BYTES);

  const int grid = NROWS / TILE_M;  // 500
  gru_fused_kernel<<<grid, THREADS, SMEM_BYTES>>>(chars, Wih, Whh, bih, bhh, out);
}

// round 5
// speedup vs baseline: 1.6865x; 1.6865x over previous
#include <cuda_runtime.h>
#include <cuda_fp16.h>
#include <cstdint>

// GRU fused kernel v2: B=16, T=60, S=2000, C=64, H=64.
// One WARP owns 16 sequences and ALL 192 gate columns -> the recurrence is
// warp-private: h lives in registers (f32 state + fp16 mma fragments derived
// in-register from the C-fragment layout), x is loaded straight from global
// into A-fragments. NO __syncthreads in the time loop; 8 independent warps
// per CTA keep the tensor pipe fed through each other's elementwise phases.
// GEMMs: fp16 m16n8k16, weights split hi+lo fp16 (exact), activations single
// fp16 -> 8 mmas per logical 16x8 k64 tile (was 12 with bf16 3-term).

namespace {

constexpr int kT = 60, kS = 2000, kC = 64, kH = 64, kG = 192;
constexpr int PITCH = 72;      // fp16 elems per weight row (144B) -> conflict-free ldsm
constexpr int THREADS = 256;   // 8 warps, 128 rows per CTA
constexpr int NROWS = 16 * 2000;

constexpr int OFF_WIH_HI = 0;
constexpr int OFF_WIH_LO = OFF_WIH_HI + kG * PITCH * 2;
constexpr int OFF_WHH_HI = OFF_WIH_LO + kG * PITCH * 2;
constexpr int OFF_WHH_LO = OFF_WHH_HI + kG * PITCH * 2;
constexpr int OFF_BRZ = OFF_WHH_LO + kG * PITCH * 2;   // f32[128]
constexpr int OFF_BIN = OFF_BRZ + 128 * 4;             // f32[64]
constexpr int OFF_BHN = OFF_BIN + 64 * 4;              // f32[64]
constexpr int SMEM_BYTES = OFF_BHN + 64 * 4;           // ~111.6 KB

__device__ __forceinline__ uint32_t smem_u32(const void* p) {
  return (uint32_t)__cvta_generic_to_shared(p);
}

__device__ __forceinline__ void ldsm4(uint32_t r[4], uint32_t addr) {
  asm volatile("ldmatrix.sync.aligned.m8n8.x4.shared.b16 {%0,%1,%2,%3}, [%4];\n"
               : "=r"(r[0]), "=r"(r[1]), "=r"(r[2]), "=r"(r[3]) : "r"(addr));
}

__device__ __forceinline__ void mma16816(float d[4], const uint32_t a[4],
                                         const uint32_t b0, const uint32_t b1) {
  asm volatile(
      "mma.sync.aligned.m16n8k16.row.col.f32.f16.f16.f32 "
      "{%0,%1,%2,%3},{%4,%5,%6,%7},{%8,%9},{%0,%1,%2,%3};\n"
      : "+f"(d[0]), "+f"(d[1]), "+f"(d[2]), "+f"(d[3])
      : "r"(a[0]), "r"(a[1]), "r"(a[2]), "r"(a[3]), "r"(b0), "r"(b1));
}

__device__ __forceinline__ uint32_t pack_f16x2(float a, float b) {
  __half2 h = __floats2half2_rn(a, b);
  return *reinterpret_cast<uint32_t*>(&h);
}

__device__ __forceinline__ float fsigmoid(float x) {
  return __fdividef(1.0f, 1.0f + __expf(-x));
}
__device__ __forceinline__ float ftanh_acc(float x) {
  return __fdividef(2.0f, 1.0f + __expf(-2.0f * x)) - 1.0f;
}

}  // namespace

__global__ void __launch_bounds__(THREADS, 1)
gru_fused_kernel(const float* __restrict__ chars,
                 const float* __restrict__ Wih,
                 const float* __restrict__ Whh,
                 const float* __restrict__ bih,
                 const float* __restrict__ bhh,
                 float* __restrict__ out) {
  extern __shared__ char smem[];
  __half* wih_hi = reinterpret_cast<__half*>(smem + OFF_WIH_HI);
  __half* wih_lo = reinterpret_cast<__half*>(smem + OFF_WIH_LO);
  __half* whh_hi = reinterpret_cast<__half*>(smem + OFF_WHH_HI);
  __half* whh_lo = reinterpret_cast<__half*>(smem + OFF_WHH_LO);
  float* brz = reinterpret_cast<float*>(smem + OFF_BRZ);
  float* bin_s = reinterpret_cast<float*>(smem + OFF_BIN);
  float* bhn_s = reinterpret_cast<float*>(smem + OFF_BHN);

  const int tid = threadIdx.x;
  const int lane = tid & 31;
  const int wid = tid >> 5;

  // ---- one-time init: split weights into fp16 hi/lo, stage biases ----
  for (int i = tid; i < kG * kC; i += THREADS) {
    const int g = i >> 6, c = i & 63;
    const float w1 = Wih[i];
    const __half h1 = __float2half_rn(w1);
    wih_hi[g * PITCH + c] = h1;
    wih_lo[g * PITCH + c] = __float2half_rn(w1 - __half2float(h1));
    const float w2 = Whh[i];
    const __half h2 = __float2half_rn(w2);
    whh_hi[g * PITCH + c] = h2;
    whh_lo[g * PITCH + c] = __float2half_rn(w2 - __half2float(h2));
  }
  if (tid < 128) brz[tid] = bih[tid] + bhh[tid];
  if (tid < 64) {
    bin_s[tid] = bih[128 + tid];
    bhn_s[tid] = bhh[128 + tid];
  }
  __syncthreads();  // the only block-wide barrier

  // ---- per-warp geometry ----
  const int warp_row0 = (blockIdx.x * 8 + wid) * 16;  // 16 rows per warp
  const int bb = warp_row0 / kS;
  const int ss = warp_row0 - bb * kS;
  const int lr = lane >> 2;          // 0..7
  const int c0 = (lane & 3) * 2;     // 0,2,4,6

  // x row pointers (rows lr and lr+8 of this warp's tile), t = 0
  const float* pxa = chars + ((size_t)bb * kT * kS + (ss + lr)) * (size_t)kC;
  const float* pxb = pxa + 8 * kC;
  const size_t tstride = (size_t)kS * kC;

  // ldsm4 lane offset for B fragments: lanes 0-7 -> (rows g0..g0+8, k 0-7),
  // 8-15 -> (g0.., k 8-15), 16-23 -> (g0+8.., k 0-7), 24-31 -> (g0+8.., k 8-15)
  const int sel = lane >> 3;
  const int b_lane_off = ((lane & 7) + 8 * (sel >> 1)) * (PITCH * 2) + (sel & 1) * 16;
  const uint32_t wihh_b = smem_u32(wih_hi) + b_lane_off;
  const uint32_t wihl_b = smem_u32(wih_lo) + b_lane_off;
  const uint32_t whhh_b = smem_u32(whh_hi) + b_lane_off;
  const uint32_t whhl_b = smem_u32(whh_lo) + b_lane_off;

  // h state: f32 C-fragment layout. hf[j][e]: tile j covers cols 8j..8j+8,
  // e0=(lr,c0) e1=(lr,c0+1) e2=(lr+8,c0) e3=(lr+8,c0+1)
  float hf[8][4];
#pragma unroll
  for (int j = 0; j < 8; ++j)
#pragma unroll
    for (int e = 0; e < 4; ++e) hf[j][e] = 0.0f;

  for (int t = 0; t < kT; ++t) {
    // ---- issue x loads early (latency hidden under h-path GEMM) ----
    float2 xv[16];
#pragma unroll
    for (int kk = 0; kk < 4; ++kk) {
      xv[4 * kk + 0] = *reinterpret_cast<const float2*>(pxa + 16 * kk + c0);
      xv[4 * kk + 1] = *reinterpret_cast<const float2*>(pxb + 16 * kk + c0);
      xv[4 * kk + 2] = *reinterpret_cast<const float2*>(pxa + 16 * kk + 8 + c0);
      xv[4 * kk + 3] = *reinterpret_cast<const float2*>(pxb + 16 * kk + 8 + c0);
    }
    pxa += tstride;
    pxb += tstride;

    // ---- accumulators: tiles 0-7 r, 8-15 z, 16-23 n(x-path); accHN h-n-path ----
    float acc[24][4];
    float accHN[8][4];
#pragma unroll
    for (int j = 0; j < 24; ++j)
#pragma unroll
      for (int e = 0; e < 4; ++e) acc[j][e] = 0.0f;
#pragma unroll
    for (int j = 0; j < 8; ++j)
#pragma unroll
      for (int e = 0; e < 4; ++e) accHN[j][e] = 0.0f;

    // ---- h-path GEMM: gh = h @ Whh^T (hi + lo weight split) ----
#pragma unroll
    for (int kk = 0; kk < 4; ++kk) {
      uint32_t ha[4];
      ha[0] = pack_f16x2(hf[2 * kk][0], hf[2 * kk][1]);
      ha[1] = pack_f16x2(hf[2 * kk][2], hf[2 * kk][3]);
      ha[2] = pack_f16x2(hf[2 * kk + 1][0], hf[2 * kk + 1][1]);
      ha[3] = pack_f16x2(hf[2 * kk + 1][2], hf[2 * kk + 1][3]);
      const int koff = kk * 32;
#pragma unroll
      for (int jp = 0; jp < 12; ++jp) {
        const int go = jp * (16 * PITCH * 2) + koff;
        uint32_t bh[4], bl[4];
        ldsm4(bh, whhh_b + go);
        ldsm4(bl, whhl_b + go);
        float* d0 = (jp < 8) ? acc[2 * jp] : accHN[2 * (jp - 8)];
        float* d1 = (jp < 8) ? acc[2 * jp + 1] : accHN[2 * (jp - 8) + 1];
        mma16816(d0, ha, bh[0], bh[1]);
        mma16816(d1, ha, bh[2], bh[3]);
        mma16816(d0, ha, bl[0], bl[1]);
        mma16816(d1, ha, bl[2], bl[3]);
      }
    }

    // ---- x-path GEMM: gi = x @ Wih^T ----
#pragma unroll
    for (int kk = 0; kk < 4; ++kk) {
      uint32_t xa[4];
      xa[0] = pack_f16x2(xv[4 * kk + 0].x, xv[4 * kk + 0].y);
      xa[1] = pack_f16x2(xv[4 * kk + 1].x, xv[4 * kk + 1].y);
      xa[2] = pack_f16x2(xv[4 * kk + 2].x, xv[4 * kk + 2].y);
      xa[3] = pack_f16x2(xv[4 * kk + 3].x, xv[4 * kk + 3].y);
      const int koff = kk * 32;
#pragma unroll
      for (int jp = 0; jp < 12; ++jp) {
        const int go = jp * (16 * PITCH * 2) + koff;
        uint32_t bh[4], bl[4];
        ldsm4(bh, wihh_b + go);
        ldsm4(bl, wihl_b + go);
        mma16816(acc[2 * jp], xa, bh[0], bh[1]);
        mma16816(acc[2 * jp + 1], xa, bh[2], bh[3]);
        mma16816(acc[2 * jp], xa, bl[0], bl[1]);
        mma16816(acc[2 * jp + 1], xa, bl[2], bl[3]);
      }
    }

    // ---- elementwise GRU update (warp-private, no sync) ----
#pragma unroll
    for (int j = 0; j < 8; ++j) {
      const float2 bR = *reinterpret_cast<const float2*>(brz + 8 * j + c0);
      const float2 bZ = *reinterpret_cast<const float2*>(brz + 64 + 8 * j + c0);
      const float2 bN = *reinterpret_cast<const float2*>(bin_s + 8 * j + c0);
      const float2 bHN = *reinterpret_cast<const float2*>(bhn_s + 8 * j + c0);
#pragma unroll
      for (int half = 0; half < 2; ++half) {
        const int e0 = half * 2, e1 = half * 2 + 1;
        const float r0 = fsigmoid(acc[j][e0] + bR.x);
        const float r1 = fsigmoid(acc[j][e1] + bR.y);
        const float z0 = fsigmoid(acc[8 + j][e0] + bZ.x);
        const float z1 = fsigmoid(acc[8 + j][e1] + bZ.y);
        const float hn0 = accHN[j][e0] + bHN.x;
        const float hn1 = accHN[j][e1] + bHN.y;
        const float n0 = ftanh_acc(acc[16 + j][e0] + bN.x + r0 * hn0);
        const float n1 = ftanh_acc(acc[16 + j][e1] + bN.y + r1 * hn1);
        hf[j][e0] = n0 + z0 * (hf[j][e0] - n0);
        hf[j][e1] = n1 + z1 * (hf[j][e1] - n1);
      }
    }
  }

  // ---- write final h (f32 state, exact) ----
  {
    float* poa = out + (size_t)(warp_row0 + lr) * kH;
    float* pob = out + (size_t)(warp_row0 + lr + 8) * kH;
#pragma unroll
    for (int j = 0; j < 8; ++j) {
      float2 va, vb;
      va.x = hf[j][0]; va.y = hf[j][1];
      vb.x = hf[j][2]; vb.y = hf[j][3];
      *reinterpret_cast<float2*>(poa + 8 * j + c0) = va;
      *reinterpret_cast<float2*>(pob + 8 * j + c0) = vb;
    }
  }
}

extern "C" void kernel_launch(void* const* d_in, const int* in_sizes, int n_in,
                              void* d_out, int out_size) {
  const float* chars = (const float*)d_in[0];
  const float* Wih = (const float*)d_in[1];
  const float* Whh = (const float*)d_in[2];
  const float* bih = (const float*)d_in[3];
  const float* bhh = (const float*)d_in[4];
  float* out = (float*)d_out;

  cudaFuncSetAttribute(gru_fused_kernel,
                       cudaFuncAttributeMaxDynamicSharedMemorySize, SMEM_BYTES);

  const int grid = NROWS / (16 * 8);  // 250 CTAs, 8 warps each, 16 rows/warp
  gru_fused_kernel<<<grid, THREADS, SMEM_BYTES>>>(chars, Wih, Whh, bih, bhh, out);
}

// round 6
// speedup vs baseline: 2.4520x; 1.4539x over previous
#include <cuda_runtime.h>
#include <cuda_fp16.h>
#include <cstdint>

// GRU fused kernel v3: B=16, T=60, S=2000, C=64, H=64.
// One WARP owns 16 sequences and ALL 192 gate columns -> warp-private
// recurrence: h lives in f32 registers (C-fragment layout == A-fragment
// layout), x loaded straight from global. No barriers in the time loop.
// v3: weights are SINGLE fp16 (lo-split dropped; rel_err budget allows it),
// halving both the mma count and the smem-crossbar (ldsm) traffic that
// co-saturated with the tensor pipe in v2. x packed to fp16 at load.

namespace {

constexpr int kT = 60, kS = 2000, kC = 64, kH = 64, kG = 192;
constexpr int PITCH = 72;      // fp16 elems per weight row (144B) -> conflict-free ldsm
constexpr int THREADS = 256;   // 8 warps, 128 rows per CTA
constexpr int NROWS = 16 * 2000;

constexpr int OFF_WIH = 0;
constexpr int OFF_WHH = OFF_WIH + kG * PITCH * 2;
constexpr int OFF_BRZ = OFF_WHH + kG * PITCH * 2;   // f32[128]
constexpr int OFF_BIN = OFF_BRZ + 128 * 4;          // f32[64]
constexpr int OFF_BHN = OFF_BIN + 64 * 4;           // f32[64]
constexpr int SMEM_BYTES = OFF_BHN + 64 * 4;        // ~56.3 KB

__device__ __forceinline__ uint32_t smem_u32(const void* p) {
  return (uint32_t)__cvta_generic_to_shared(p);
}

__device__ __forceinline__ void ldsm4(uint32_t r[4], uint32_t addr) {
  asm volatile("ldmatrix.sync.aligned.m8n8.x4.shared.b16 {%0,%1,%2,%3}, [%4];\n"
               : "=r"(r[0]), "=r"(r[1]), "=r"(r[2]), "=r"(r[3]) : "r"(addr));
}

__device__ __forceinline__ void mma16816(float d[4], const uint32_t a[4],
                                         const uint32_t b0, const uint32_t b1) {
  asm volatile(
      "mma.sync.aligned.m16n8k16.row.col.f32.f16.f16.f32 "
      "{%0,%1,%2,%3},{%4,%5,%6,%7},{%8,%9},{%0,%1,%2,%3};\n"
      : "+f"(d[0]), "+f"(d[1]), "+f"(d[2]), "+f"(d[3])
      : "r"(a[0]), "r"(a[1]), "r"(a[2]), "r"(a[3]), "r"(b0), "r"(b1));
}

__device__ __forceinline__ uint32_t pack_f16x2(float a, float b) {
  __half2 h = __floats2half2_rn(a, b);
  return *reinterpret_cast<uint32_t*>(&h);
}

__device__ __forceinline__ float fsigmoid(float x) {
  return __fdividef(1.0f, 1.0f + __expf(-x));
}
__device__ __forceinline__ float ftanh_acc(float x) {
  return __fdividef(2.0f, 1.0f + __expf(-2.0f * x)) - 1.0f;
}

}  // namespace

__global__ void __launch_bounds__(THREADS, 1)
gru_fused_kernel(const float* __restrict__ chars,
                 const float* __restrict__ Wih,
                 const float* __restrict__ Whh,
                 const float* __restrict__ bih,
                 const float* __restrict__ bhh,
                 float* __restrict__ out) {
  extern __shared__ char smem[];
  __half* wih_s = reinterpret_cast<__half*>(smem + OFF_WIH);
  __half* whh_s = reinterpret_cast<__half*>(smem + OFF_WHH);
  float* brz = reinterpret_cast<float*>(smem + OFF_BRZ);
  float* bin_s = reinterpret_cast<float*>(smem + OFF_BIN);
  float* bhn_s = reinterpret_cast<float*>(smem + OFF_BHN);

  const int tid = threadIdx.x;
  const int lane = tid & 31;
  const int wid = tid >> 5;

  // ---- one-time init: fp16 weights (padded pitch), biases ----
  for (int i = tid; i < kG * kC; i += THREADS) {
    const int g = i >> 6, c = i & 63;
    wih_s[g * PITCH + c] = __float2half_rn(Wih[i]);
    whh_s[g * PITCH + c] = __float2half_rn(Whh[i]);
  }
  if (tid < 128) brz[tid] = bih[tid] + bhh[tid];
  if (tid < 64) {
    bin_s[tid] = bih[128 + tid];
    bhn_s[tid] = bhh[128 + tid];
  }
  __syncthreads();  // the only block-wide barrier

  // ---- per-warp geometry ----
  const int warp_row0 = (blockIdx.x * 8 + wid) * 16;  // 16 rows per warp
  const int bb = warp_row0 / kS;
  const int ss = warp_row0 - bb * kS;
  const int lr = lane >> 2;          // 0..7
  const int c0 = (lane & 3) * 2;     // 0,2,4,6

  const float* pxa = chars + ((size_t)bb * kT * kS + (ss + lr)) * (size_t)kC;
  const float* pxb = pxa + 8 * kC;
  const size_t tstride = (size_t)kS * kC;

  // ldsm4 lane offset for B fragments
  const int sel = lane >> 3;
  const int b_lane_off = ((lane & 7) + 8 * (sel >> 1)) * (PITCH * 2) + (sel & 1) * 16;
  const uint32_t wih_b = smem_u32(wih_s) + b_lane_off;
  const uint32_t whh_b = smem_u32(whh_s) + b_lane_off;

  // h state in f32 C-fragment layout; tile j covers cols 8j..8j+7
  float hf[8][4];
#pragma unroll
  for (int j = 0; j < 8; ++j)
#pragma unroll
    for (int e = 0; e < 4; ++e) hf[j][e] = 0.0f;

  for (int t = 0; t < kT; ++t) {
    // ---- load x_t and pack to fp16 A-fragments immediately ----
    uint32_t xa[4][4];  // [kk][frag]
#pragma unroll
    for (int kk = 0; kk < 4; ++kk) {
      const float2 v0 = *reinterpret_cast<const float2*>(pxa + 16 * kk + c0);
      const float2 v1 = *reinterpret_cast<const float2*>(pxb + 16 * kk + c0);
      const float2 v2 = *reinterpret_cast<const float2*>(pxa + 16 * kk + 8 + c0);
      const float2 v3 = *reinterpret_cast<const float2*>(pxb + 16 * kk + 8 + c0);
      xa[kk][0] = pack_f16x2(v0.x, v0.y);
      xa[kk][1] = pack_f16x2(v1.x, v1.y);
      xa[kk][2] = pack_f16x2(v2.x, v2.y);
      xa[kk][3] = pack_f16x2(v3.x, v3.y);
    }
    pxa += tstride;
    pxb += tstride;

    // pack h A-fragments (C-frag layout matches A-frag layout)
    uint32_t ha[4][4];
#pragma unroll
    for (int kk = 0; kk < 4; ++kk) {
      ha[kk][0] = pack_f16x2(hf[2 * kk][0], hf[2 * kk][1]);
      ha[kk][1] = pack_f16x2(hf[2 * kk][2], hf[2 * kk][3]);
      ha[kk][2] = pack_f16x2(hf[2 * kk + 1][0], hf[2 * kk + 1][1]);
      ha[kk][3] = pack_f16x2(hf[2 * kk + 1][2], hf[2 * kk + 1][3]);
    }

    // accumulators: tiles 0-7 r, 8-15 z, 16-23 n(x-path); accHN = h-n-path
    float acc[24][4];
    float accHN[8][4];
#pragma unroll
    for (int j = 0; j < 24; ++j)
#pragma unroll
      for (int e = 0; e < 4; ++e) acc[j][e] = 0.0f;
#pragma unroll
    for (int j = 0; j < 8; ++j)
#pragma unroll
      for (int e = 0; e < 4; ++e) accHN[j][e] = 0.0f;

    // ---- h-path GEMM: gh = h @ Whh^T (prefetch next B one step ahead) ----
    {
      uint32_t bcur[4], bnext[4];
      ldsm4(bcur, whh_b);  // kk=0, jp=0
#pragma unroll
      for (int kk = 0; kk < 4; ++kk) {
        const int koff = kk * 32;
#pragma unroll
        for (int jp = 0; jp < 12; ++jp) {
          // prefetch next (kk,jp)
          const int nkk = (jp == 11) ? kk + 1 : kk;
          const int njp = (jp == 11) ? 0 : jp + 1;
          if (!(kk == 3 && jp == 11)) {
            ldsm4(bnext, whh_b + nkk * 32 + njp * (16 * PITCH * 2));
          }
          float* d0 = (jp < 8) ? acc[2 * jp] : accHN[2 * (jp - 8)];
          float* d1 = (jp < 8) ? acc[2 * jp + 1] : accHN[2 * (jp - 8) + 1];
          mma16816(d0, ha[kk], bcur[0], bcur[1]);
          mma16816(d1, ha[kk], bcur[2], bcur[3]);
          bcur[0] = bnext[0]; bcur[1] = bnext[1];
          bcur[2] = bnext[2]; bcur[3] = bnext[3];
        }
        (void)koff;
      }
    }

    // ---- x-path GEMM: gi = x @ Wih^T ----
    {
      uint32_t bcur[4], bnext[4];
      ldsm4(bcur, wih_b);
#pragma unroll
      for (int kk = 0; kk < 4; ++kk) {
#pragma unroll
        for (int jp = 0; jp < 12; ++jp) {
          const int nkk = (jp == 11) ? kk + 1 : kk;
          const int njp = (jp == 11) ? 0 : jp + 1;
          if (!(kk == 3 && jp == 11)) {
            ldsm4(bnext, wih_b + nkk * 32 + njp * (16 * PITCH * 2));
          }
          mma16816(acc[2 * jp], xa[kk], bcur[0], bcur[1]);
          mma16816(acc[2 * jp + 1], xa[kk], bcur[2], bcur[3]);
          bcur[0] = bnext[0]; bcur[1] = bnext[1];
          bcur[2] = bnext[2]; bcur[3] = bnext[3];
        }
      }
    }

    // ---- elementwise GRU update (warp-private, no sync) ----
#pragma unroll
    for (int j = 0; j < 8; ++j) {
      const float2 bR = *reinterpret_cast<const float2*>(brz + 8 * j + c0);
      const float2 bZ = *reinterpret_cast<const float2*>(brz + 64 + 8 * j + c0);
      const float2 bN = *reinterpret_cast<const float2*>(bin_s + 8 * j + c0);
      const float2 bHN = *reinterpret_cast<const float2*>(bhn_s + 8 * j + c0);
#pragma unroll
      for (int half = 0; half < 2; ++half) {
        const int e0 = half * 2, e1 = half * 2 + 1;
        const float r0 = fsigmoid(acc[j][e0] + bR.x);
        const float r1 = fsigmoid(acc[j][e1] + bR.y);
        const float z0 = fsigmoid(acc[8 + j][e0] + bZ.x);
        const float z1 = fsigmoid(acc[8 + j][e1] + bZ.y);
        const float hn0 = accHN[j][e0] + bHN.x;
        const float hn1 = accHN[j][e1] + bHN.y;
        const float n0 = ftanh_acc(acc[16 + j][e0] + bN.x + r0 * hn0);
        const float n1 = ftanh_acc(acc[16 + j][e1] + bN.y + r1 * hn1);
        hf[j][e0] = n0 + z0 * (hf[j][e0] - n0);
        hf[j][e1] = n1 + z1 * (hf[j][e1] - n1);
      }
    }
  }

  // ---- write final h (f32 state, exact) ----
  {
    float* poa = out + (size_t)(warp_row0 + lr) * kH;
    float* pob = out + (size_t)(warp_row0 + lr + 8) * kH;
#pragma unroll
    for (int j = 0; j < 8; ++j) {
      float2 va, vb;
      va.x = hf[j][0]; va.y = hf[j][1];
      vb.x = hf[j][2]; vb.y = hf[j][3];
      *reinterpret_cast<float2*>(poa + 8 * j + c0) = va;
      *reinterpret_cast<float2*>(pob + 8 * j + c0) = vb;
    }
  }
}

extern "C" void kernel_launch(void* const* d_in, const int* in_sizes, int n_in,
                              void* d_out, int out_size) {
  const float* chars = (const float*)d_in[0];
  const float* Wih = (const float*)d_in[1];
  const float* Whh = (const float*)d_in[2];
  const float* bih = (const float*)d_in[3];
  const float* bhh = (const float*)d_in[4];
  float* out = (float*)d_out;

  cudaFuncSetAttribute(gru_fused_kernel,
                       cudaFuncAttributeMaxDynamicSharedMemorySize, SMEM_BYTES);

  const int grid = NROWS / (16 * 8);  // 250 CTAs, 8 warps each, 16 rows/warp
  gru_fused_kernel<<<grid, THREADS, SMEM_BYTES>>>(chars, Wih, Whh, bih, bhh, out);
}